// round 1
// baseline (speedup 1.0000x reference)
#include <cuda_runtime.h>
#include <cstdint>
#include <cstddef>

#define NN 50000
#define NE 800000
#define NG 512
#define DD 101
#define PP 104   // padded row pitch for D=101 (multiple of 4 for float4/red.v4)

// ---------------- scratch (device globals; no allocation allowed) ----------------
__device__ float g_xp [NN * PP];   // x padded to pitch 104 (zero pad cols)
__device__ float g_agg[NN * PP];   // message aggregation buffer (reused layer1/2)
__device__ float g_t  [NN * PP];   // MLP intermediate
__device__ float g_h1 [NN * PP];   // layer-1 output (padded, zero pad cols)
__device__ float g_gp [NG * 200];  // pooled per-graph features

// ---------------- helpers ----------------
__device__ __forceinline__ void red4(float* p, float a, float b, float c, float d) {
    asm volatile("red.global.add.v4.f32 [%0], {%1,%2,%3,%4};"
                 :: "l"(p), "f"(a), "f"(b), "f"(c), "f"(d) : "memory");
}

__global__ void pad_x_kernel(const float* __restrict__ x) {
    int t = blockIdx.x * blockDim.x + threadIdx.x;
    if (t < NN * PP) {
        int node = t / PP;
        int c    = t - node * PP;
        g_xp[t] = (c < DD) ? x[(size_t)node * DD + c] : 0.f;
    }
}

// ---------------- fused GEMM kernel ----------------
// C = A1(+A2) @ B ; tile 128x128x8, 256 threads, 8x8 microtile.
// Row/col microtile mapping: R(i) = ty*4+i (i<4) else 64+ty*4+(i-4); same for cols with tx.
// MODE 0: out[m][n] = relu(C + bias)   (store, zero-fill padding cols up to pOut)
// MODE 1: edge message: v = relu(C + bias + xg[src[m]][n]); red.v4 into outp[dst[m]]
// MODE 2: pooled:       v = relu(C + bias);                 red.v4 into outp[idx0[m]] (idx0=batch)
template <int MODE>
__global__ __launch_bounds__(256, 2)
void gemm_fused(const float* __restrict__ A1, int pA1,
                const float* __restrict__ A2, int pA2,
                const float* __restrict__ B,
                const float* __restrict__ bias,
                int M, int N, int K,
                const int* __restrict__ idx0,   // src (MODE1) / batch (MODE2)
                const int* __restrict__ idx1,   // dst (MODE1)
                const float* __restrict__ xg, int pXg,
                float* __restrict__ outp, int pOut)
{
    __shared__ float As[8][132];
    __shared__ float Bs[8][132];

    const int tid = threadIdx.x;
    const int tx  = tid & 15;
    const int ty  = tid >> 4;
    const int m0  = blockIdx.x * 128;
    const int n0  = blockIdx.y * 128;

    float acc[8][8];
#pragma unroll
    for (int i = 0; i < 8; ++i)
#pragma unroll
        for (int j = 0; j < 8; ++j) acc[i][j] = 0.f;

    const int aRow = tid >> 1;        // 0..127
    const int aK4  = (tid & 1) * 4;   // 0 or 4
    const int bK   = tid >> 5;        // 0..7
    const int bN4  = (tid & 31) * 4;  // 0..124

    const int ktiles = (K + 7) >> 3;
    for (int kt = 0; kt < ktiles; ++kt) {
        const int k0 = kt << 3;
        // --- load A tile (transposed into As[k][m]) ---
        {
            const int gm = m0 + aRow;
            float v[4];
#pragma unroll
            for (int u = 0; u < 4; ++u) {
                const int gk = k0 + aK4 + u;
                float t = 0.f;
                if (gm < M && gk < K) {
                    t = __ldg(&A1[(size_t)gm * pA1 + gk]);
                    if (A2) t += __ldg(&A2[(size_t)gm * pA2 + gk]);
                }
                v[u] = t;
            }
            As[aK4 + 0][aRow] = v[0];
            As[aK4 + 1][aRow] = v[1];
            As[aK4 + 2][aRow] = v[2];
            As[aK4 + 3][aRow] = v[3];
        }
        // --- load B tile ---
        {
            const int gk = k0 + bK;
            float v[4];
#pragma unroll
            for (int u = 0; u < 4; ++u) {
                const int gn = n0 + bN4 + u;
                v[u] = (gk < K && gn < N) ? __ldg(&B[(size_t)gk * N + gn]) : 0.f;
            }
            *reinterpret_cast<float4*>(&Bs[bK][bN4]) = make_float4(v[0], v[1], v[2], v[3]);
        }
        __syncthreads();
#pragma unroll
        for (int kk = 0; kk < 8; ++kk) {
            float4 a0 = *reinterpret_cast<const float4*>(&As[kk][ty * 4]);
            float4 a1 = *reinterpret_cast<const float4*>(&As[kk][64 + ty * 4]);
            float4 b0 = *reinterpret_cast<const float4*>(&Bs[kk][tx * 4]);
            float4 b1 = *reinterpret_cast<const float4*>(&Bs[kk][64 + tx * 4]);
            float a[8] = {a0.x, a0.y, a0.z, a0.w, a1.x, a1.y, a1.z, a1.w};
            float b[8] = {b0.x, b0.y, b0.z, b0.w, b1.x, b1.y, b1.z, b1.w};
#pragma unroll
            for (int i = 0; i < 8; ++i)
#pragma unroll
                for (int j = 0; j < 8; ++j)
                    acc[i][j] = fmaf(a[i], b[j], acc[i][j]);
        }
        __syncthreads();
    }

    // ---------------- epilogue ----------------
    if (MODE == 0) {
#pragma unroll
        for (int i = 0; i < 8; ++i) {
            const int m = m0 + ((i < 4) ? (ty * 4 + i) : (60 + ty * 4 + i));
            if (m >= M) continue;
#pragma unroll
            for (int j = 0; j < 8; ++j) {
                const int n = n0 + ((j < 4) ? (tx * 4 + j) : (60 + tx * 4 + j));
                if (n < pOut) {
                    float v = (n < N) ? fmaxf(acc[i][j] + bias[n], 0.f) : 0.f;
                    outp[(size_t)m * pOut + n] = v;
                }
            }
        }
    } else {
        const int nb1 = n0 + tx * 4;
        const int nb2 = n0 + 64 + tx * 4;
        const int lim = (MODE == 1) ? pOut : N;
        const bool do1 = (nb1 < lim);
        const bool do2 = (nb2 < lim);

        float bi[8];
#pragma unroll
        for (int j = 0; j < 8; ++j) {
            const int n = n0 + ((j < 4) ? (tx * 4 + j) : (60 + tx * 4 + j));
            bi[j] = (n < N) ? bias[n] : 0.f;
        }

#pragma unroll
        for (int i = 0; i < 8; ++i) {
            const int m = m0 + ((i < 4) ? (ty * 4 + i) : (60 + ty * 4 + i));
            if (m >= M) continue;

            if (MODE == 1) {
                const int s = idx0[m];
                const int d = idx1[m];
                const float* xr = xg + (size_t)s * pXg;
                float4 x0 = make_float4(0.f, 0.f, 0.f, 0.f);
                float4 x1 = make_float4(0.f, 0.f, 0.f, 0.f);
                if (do1) x0 = *reinterpret_cast<const float4*>(xr + nb1);
                if (do2) x1 = *reinterpret_cast<const float4*>(xr + nb2);
                float v0 = fmaxf(acc[i][0] + bi[0] + x0.x, 0.f);
                float v1 = fmaxf(acc[i][1] + bi[1] + x0.y, 0.f);
                float v2 = fmaxf(acc[i][2] + bi[2] + x0.z, 0.f);
                float v3 = fmaxf(acc[i][3] + bi[3] + x0.w, 0.f);
                float v4 = fmaxf(acc[i][4] + bi[4] + x1.x, 0.f);
                float v5 = fmaxf(acc[i][5] + bi[5] + x1.y, 0.f);
                float v6 = fmaxf(acc[i][6] + bi[6] + x1.z, 0.f);
                float v7 = fmaxf(acc[i][7] + bi[7] + x1.w, 0.f);
                float* dp = outp + (size_t)d * pOut;
                if (do1) red4(dp + nb1, v0, v1, v2, v3);
                if (do2) red4(dp + nb2, v4, v5, v6, v7);
            } else {  // MODE 2
                const int gidx = idx0[m];
                float v[8];
#pragma unroll
                for (int j = 0; j < 8; ++j) v[j] = fmaxf(acc[i][j] + bi[j], 0.f);
                float* dp = outp + (size_t)gidx * pOut;
                if (do1) red4(dp + nb1, v[0], v[1], v[2], v[3]);
                if (do2) red4(dp + nb2, v[4], v[5], v[6], v[7]);
            }
        }
    }
}

// ---------------- head: g -> relu(g@Wl+bl) -> @Wl2+bl2 -> abs ----------------
__global__ void final_kernel(const float* __restrict__ g,
                             const float* __restrict__ Wl, const float* __restrict__ bl,
                             const float* __restrict__ Wl2, const float* __restrict__ bl2,
                             float* __restrict__ out)
{
    __shared__ float sg[200];
    __shared__ float s2[50];
    const int b = blockIdx.x;
    for (int i = threadIdx.x; i < 200; i += blockDim.x) sg[i] = g[(size_t)b * 200 + i];
    __syncthreads();
    if (threadIdx.x < 50) {
        float acc = bl[threadIdx.x];
        for (int k = 0; k < 200; ++k) acc = fmaf(sg[k], Wl[(size_t)k * 50 + threadIdx.x], acc);
        s2[threadIdx.x] = fmaxf(acc, 0.f);
    }
    __syncthreads();
    if (threadIdx.x == 0) {
        float o = bl2[0];
        for (int k = 0; k < 50; ++k) o = fmaf(s2[k], Wl2[k], o);
        out[b] = fabsf(o);
    }
}

// ---------------- launch ----------------
extern "C" void kernel_launch(void* const* d_in, const int* in_sizes, int n_in,
                              void* d_out, int out_size)
{
    const float* x    = (const float*)d_in[0];
    const int*   ei   = (const int*)  d_in[1];
    // d_in[2] = edge_type (unused)
    const float* ea   = (const float*)d_in[3];
    const int*   batch= (const int*)  d_in[4];
    const float* We1  = (const float*)d_in[5];
    const float* be1  = (const float*)d_in[6];
    const float* W1a  = (const float*)d_in[7];
    const float* b1a  = (const float*)d_in[8];
    const float* W1b  = (const float*)d_in[9];
    const float* b1b  = (const float*)d_in[10];
    const float* We2  = (const float*)d_in[11];
    const float* be2  = (const float*)d_in[12];
    const float* W2a  = (const float*)d_in[13];
    const float* b2a  = (const float*)d_in[14];
    const float* W2b  = (const float*)d_in[15];
    const float* b2b  = (const float*)d_in[16];
    const float* Wl   = (const float*)d_in[17];
    const float* bl   = (const float*)d_in[18];
    const float* Wl2  = (const float*)d_in[19];
    const float* bl2  = (const float*)d_in[20];

    const int* src = ei;
    const int* dst = ei + NE;

    float *xp, *agg, *tt, *h1, *gp;
    cudaGetSymbolAddress((void**)&xp,  g_xp);
    cudaGetSymbolAddress((void**)&agg, g_agg);
    cudaGetSymbolAddress((void**)&tt,  g_t);
    cudaGetSymbolAddress((void**)&h1,  g_h1);
    cudaGetSymbolAddress((void**)&gp,  g_gp);

    const int nodeBlocks = (NN + 127) / 128;

    // pad x into pitch-104 buffer (zeros in pad cols)
    pad_x_kernel<<<(NN * PP + 255) / 256, 256>>>(x);

    // ---- layer 1 ----
    cudaMemsetAsync(agg, 0, sizeof(float) * NN * PP);
    gemm_fused<1><<<dim3(NE / 128, 1), 256>>>(ea, DD, nullptr, 0, We1, be1,
                                              NE, DD, DD, src, dst, xp, PP, agg, PP);
    gemm_fused<0><<<dim3(nodeBlocks, 1), 256>>>(x, DD, agg, PP, W1a, b1a,
                                                NN, DD, DD, nullptr, nullptr, nullptr, 0, tt, PP);
    gemm_fused<0><<<dim3(nodeBlocks, 1), 256>>>(tt, PP, nullptr, 0, W1b, b1b,
                                                NN, DD, DD, nullptr, nullptr, nullptr, 0, h1, PP);

    // ---- layer 2 ----
    cudaMemsetAsync(agg, 0, sizeof(float) * NN * PP);
    gemm_fused<1><<<dim3(NE / 128, 1), 256>>>(ea, DD, nullptr, 0, We2, be2,
                                              NE, DD, DD, src, dst, h1, PP, agg, PP);
    gemm_fused<0><<<dim3(nodeBlocks, 1), 256>>>(h1, PP, agg, PP, W2a, b2a,
                                                NN, 100, DD, nullptr, nullptr, nullptr, 0, tt, PP);
    cudaMemsetAsync(gp, 0, sizeof(float) * NG * 200);
    gemm_fused<2><<<dim3(nodeBlocks, 2), 256>>>(tt, PP, nullptr, 0, W2b, b2b,
                                                NN, 200, 100, batch, nullptr, nullptr, 0, gp, 200);

    // ---- head ----
    final_kernel<<<NG, 64>>>(gp, Wl, bl, Wl2, bl2, (float*)d_out);
}

// round 9
// speedup vs baseline: 1.4958x; 1.4958x over previous
#include <cuda_runtime.h>
#include <cuda_bf16.h>
#include <cstdint>
#include <cstddef>

#define NN   50000
#define NNP  50048      // padded rows (multiple of 128)
#define NE   800000
#define NG   512
#define DD   101
#define PP   104        // plain fp32 pitch (16B-aligned rows: 104*4=416)
#define RS   112        // split region size (bf16 cols per half; 7 k16-tiles)
#define PA   224        // split bf16 pitch = 2*RS (448B rows, 16B aligned)
#define NKT  21         // logical k16 tiles = 3 regions * 7

// smem partition (bytes)
#define SM_AS   12288              // uint32 As[2][128][12]
#define SM_WC   60928              // uint32 Wc[2][56][136]
#define SM_ALL  (SM_AS + SM_WC + 512)

// ---------------- scratch (device globals; zero-initialized; no allocation) ------
__device__ __nv_bfloat16 g_ea2[(size_t)NE * PA];   // edge_attr split [hi|lo] bf16
__device__ __nv_bfloat16 g_as [(size_t)NNP * PA];  // node GEMM input split (reused)
__device__ float g_xp [(size_t)NNP * PP];          // x padded, plain fp32
__device__ float g_agg[(size_t)NNP * PP];          // scatter-add target
__device__ float g_t  [(size_t)NNP * PP];          // MLP intermediate (plain)
__device__ float g_h1 [(size_t)NNP * PP];          // layer-1 output (plain)
__device__ float g_gp [NG * 200];                  // pooled per-graph features

// ---------------- helpers ----------------
__device__ __forceinline__ void red4(float* p, float a, float b, float c, float d) {
    asm volatile("red.global.add.v4.f32 [%0], {%1,%2,%3,%4};"
                 :: "l"(p), "f"(a), "f"(b), "f"(c), "f"(d) : "memory");
}

__device__ __forceinline__ uint32_t packbf(float e, float o) {
    __nv_bfloat162 t = __floats2bfloat162_rn(e, o);   // e -> low 16 bits (k even)
    return *reinterpret_cast<uint32_t*>(&t);
}

// split pair (v0,v1) into bf16 hi-pair and lo-pair (packed u32 each)
__device__ __forceinline__ void bsplit2(float v0, float v1, uint32_t& hi, uint32_t& lo) {
    float h0 = __bfloat162float(__float2bfloat16(v0));
    float h1 = __bfloat162float(__float2bfloat16(v1));
    hi = packbf(h0, h1);
    lo = packbf(v0 - h0, v1 - h1);
}

__device__ __forceinline__ void mma16816(float c[4],
                                         uint32_t a0, uint32_t a1, uint32_t a2, uint32_t a3,
                                         uint32_t b0, uint32_t b1) {
    asm volatile(
        "mma.sync.aligned.m16n8k16.row.col.f32.bf16.bf16.f32 "
        "{%0,%1,%2,%3}, {%4,%5,%6,%7}, {%8,%9}, {%0,%1,%2,%3};"
        : "+f"(c[0]), "+f"(c[1]), "+f"(c[2]), "+f"(c[3])
        : "r"(a0), "r"(a1), "r"(a2), "r"(a3), "r"(b0), "r"(b1));
}

// ---------------- prep kernels ----------------
// plain pad: src [rows x srcPitch] -> dst [rows x PP] fp32 (zeros in pad cols)
__global__ void pad_plain_kernel(float* __restrict__ dst, const float* __restrict__ src,
                                 int rows, int srcPitch) {
    int t = blockIdx.x * blockDim.x + threadIdx.x;
    if (t < rows * PP) {
        int r = t / PP;
        int c = t - r * PP;
        dst[t] = (c < srcPitch) ? __ldg(&src[(size_t)r * srcPitch + c]) : 0.f;
    }
}

// split: src plain [rows x srcPitch] fp32 -> dst [rows x PA] bf16 [hi(112)|lo(112)]
__global__ void split_pair_kernel(__nv_bfloat16* __restrict__ dst,
                                  const float* __restrict__ src,
                                  int rows, int srcPitch) {
    long long t = (long long)blockIdx.x * blockDim.x + threadIdx.x;
    if (t >= (long long)rows * 56) return;
    int r  = (int)(t / 56);
    int c2 = (int)(t % 56) * 2;
    float v0 = (c2     < srcPitch) ? __ldg(&src[(size_t)r * srcPitch + c2    ]) : 0.f;
    float v1 = (c2 + 1 < srcPitch) ? __ldg(&src[(size_t)r * srcPitch + c2 + 1]) : 0.f;
    uint32_t hi, lo;
    bsplit2(v0, v1, hi, lo);
    uint32_t* d32 = reinterpret_cast<uint32_t*>(dst + (size_t)r * PA);
    d32[c2 / 2]      = hi;
    d32[56 + c2 / 2] = lo;
}

// dst = split(a + b), a/b plain [NN x PP]
__global__ void add_split_kernel(__nv_bfloat16* __restrict__ dst,
                                 const float* __restrict__ a,
                                 const float* __restrict__ b) {
    long long t = (long long)blockIdx.x * blockDim.x + threadIdx.x;
    if (t >= (long long)NN * 56) return;
    int r  = (int)(t / 56);
    int c2 = (int)(t % 56) * 2;
    float v0 = 0.f, v1 = 0.f;
    if (c2 < PP)     v0 = a[(size_t)r * PP + c2]     + b[(size_t)r * PP + c2];
    if (c2 + 1 < PP) v1 = a[(size_t)r * PP + c2 + 1] + b[(size_t)r * PP + c2 + 1];
    uint32_t hi, lo;
    bsplit2(v0, v1, hi, lo);
    uint32_t* d32 = reinterpret_cast<uint32_t*>(dst + (size_t)r * PA);
    d32[c2 / 2]      = hi;
    d32[56 + c2 / 2] = lo;
}

// ---------------- 3xBF16 (K-expanded) tensor-core GEMM, fused epilogues ----------
// Logical K = 336 (3 regions of 112): A regions [hi|lo|hi], B regions [hi|hi|lo]
// => sum = hiA*hiB + loA*hiB + hiA*loB  (near-fp32 product accuracy)
// Block 128x128, 8 warps, warp tile 32x64. A via cp.async double buffer;
// full weight tile (hi+lo) cached in smem once per block.
// MODE 0: outp[m][n] = relu(C+bias), plain fp32, zeros in pad cols up to pOut
// MODE 1: v = relu(C+bias+xg[idx0[m]][n]); red4 into outp[idx1[m]]  (edge message)
// MODE 2: v = relu(C+bias);                red4 into outp[idx0[m]]  (pool by batch)
template <int MODE>
__global__ __launch_bounds__(256, 2)
void gemm_bf3(const __nv_bfloat16* __restrict__ A,   // [M x PA] split bf16
              const float* __restrict__ B,           // [Korig x N] fp32 weights
              const float* __restrict__ bias,
              int M, int N, int Korig,
              const int* __restrict__ idx0, const int* __restrict__ idx1,
              const float* __restrict__ xg,          // plain fp32 [x PP]
              float* __restrict__ outp, int pOut)
{
    extern __shared__ char sm[];
    uint32_t* AsU   = reinterpret_cast<uint32_t*>(sm);            // [2][128][12]
    uint32_t* WcU   = reinterpret_cast<uint32_t*>(sm + SM_AS);    // [2][56][136]
    float*    biasS = reinterpret_cast<float*>(sm + SM_AS + SM_WC);

    const int tid  = threadIdx.x;
    const int m0   = blockIdx.x * 128;
    const int n0   = blockIdx.y * 128;
    const int wid  = tid >> 5;
    const int lane = tid & 31;
    const int wm   = (wid >> 1) * 32;
    const int wn   = (wid & 1) * 64;
    const int g    = lane >> 2;
    const int tg   = lane & 3;

    // A cp.async mapping: 2 threads per row, 16B each (32B = 16 bf16 per row-tile)
    const int arow = tid >> 1;
    const int aoff = (tid & 1);   // 0/1 -> +0/+16 bytes

    const char* Abase = reinterpret_cast<const char*>(A) + (size_t)(m0 + arow) * (PA * 2);

    // issue A tile kt into stage st
    auto issueA = [&](int kt, int st) {
        int r = (kt >= 14) ? 2 : (kt >= 7 ? 1 : 0);
        int q = kt - ((r == 2) ? 14 : (r == 1 ? 7 : 0));
        int physB = ((r == 1) ? (RS * 2) : 0) + q * 32 + aoff * 16;
        uint32_t sdst = (uint32_t)__cvta_generic_to_shared(
            AsU + st * (128 * 12) + arow * 12 + aoff * 4);
        asm volatile("cp.async.cg.shared.global [%0], [%1], 16;"
                     :: "r"(sdst), "l"(Abase + physB));
        asm volatile("cp.async.commit_group;");
    };

    issueA(0, 0);   // overlap with weight-cache fill

    // ---- fill weight cache: hi set + lo set, packed bf16 pairs ----
    for (int it = tid; it < 56 * 128; it += 256) {
        int kp = it >> 7, n = it & 127;
        int ke = kp * 2, ko = ke + 1;
        bool nv = (n0 + n < N);
        float we = (nv && ke < Korig) ? __ldg(&B[(size_t)ke * N + n0 + n]) : 0.f;
        float wo = (nv && ko < Korig) ? __ldg(&B[(size_t)ko * N + n0 + n]) : 0.f;
        uint32_t hi, lo;
        bsplit2(we, wo, hi, lo);
        WcU[kp * 136 + n]            = hi;
        WcU[56 * 136 + kp * 136 + n] = lo;
    }
    if (tid < 128) biasS[tid] = (n0 + tid < N) ? __ldg(&bias[n0 + tid]) : 0.f;

    float acc[2][8][4];
#pragma unroll
    for (int i = 0; i < 2; ++i)
#pragma unroll
        for (int j = 0; j < 8; ++j)
#pragma unroll
            for (int q = 0; q < 4; ++q) acc[i][j][q] = 0.f;

    for (int kt = 0; kt < NKT; ++kt) {
        const int st = kt & 1;
        asm volatile("cp.async.wait_group 0;");
        __syncthreads();
        if (kt + 1 < NKT) issueA(kt + 1, st ^ 1);

        const int r   = (kt >= 14) ? 2 : (kt >= 7 ? 1 : 0);
        const int q   = kt - ((r == 2) ? 14 : (r == 1 ? 7 : 0));
        const uint32_t* wb = WcU + ((r == 2) ? 56 * 136 : 0) + (q * 8) * 136;

        uint32_t bfr[8][2];
#pragma unroll
        for (int j = 0; j < 8; ++j) {
            const int col = wn + j * 8 + g;
            bfr[j][0] = wb[tg * 136 + col];
            bfr[j][1] = wb[(tg + 4) * 136 + col];
        }
        const uint32_t* as = AsU + st * (128 * 12);
#pragma unroll
        for (int i = 0; i < 2; ++i) {
            const int mb = wm + i * 16 + g;
            uint32_t a0 = as[mb * 12 + tg];
            uint32_t a1 = as[(mb + 8) * 12 + tg];
            uint32_t a2 = as[mb * 12 + tg + 4];
            uint32_t a3 = as[(mb + 8) * 12 + tg + 4];
#pragma unroll
            for (int j = 0; j < 8; ++j)
                mma16816(acc[i][j], a0, a1, a2, a3, bfr[j][0], bfr[j][1]);
        }
        __syncthreads();
    }

    // ---------------- epilogue ----------------
    if (MODE == 0) {
#pragma unroll
        for (int i = 0; i < 2; ++i) {
            const int rl = m0 + wm + i * 16 + g;
            const int rh = rl + 8;
#pragma unroll
            for (int j = 0; j < 8; ++j) {
                const int nl = wn + j * 8 + tg * 2;
                const int n  = n0 + nl;
                if (n < pOut) {
                    if (rl < M) {
                        float2 v;
                        v.x = fmaxf(acc[i][j][0] + biasS[nl], 0.f);
                        v.y = fmaxf(acc[i][j][1] + biasS[nl + 1], 0.f);
                        *reinterpret_cast<float2*>(&outp[(size_t)rl * pOut + n]) = v;
                    }
                    if (rh < M) {
                        float2 v;
                        v.x = fmaxf(acc[i][j][2] + biasS[nl], 0.f);
                        v.y = fmaxf(acc[i][j][3] + biasS[nl + 1], 0.f);
                        *reinterpret_cast<float2*>(&outp[(size_t)rh * pOut + n]) = v;
                    }
                }
            }
        }
    } else {
#pragma unroll
        for (int i = 0; i < 2; ++i) {
#pragma unroll
            for (int half = 0; half < 2; ++half) {
                const int r = m0 + wm + i * 16 + g + half * 8;
                const bool rv = (r < M);
                int s_ = 0, d_ = 0;
                if (rv) {
                    if (MODE == 1) { s_ = idx0[r]; d_ = idx1[r]; }
                    else           { d_ = idx0[r]; }
                }
#pragma unroll
                for (int j = 0; j < 8; ++j) {
                    const int nl = wn + j * 8 + tg * 2;
                    float v0 = acc[i][j][half * 2 + 0] + biasS[nl];
                    float v1 = acc[i][j][half * 2 + 1] + biasS[nl + 1];
                    // repack: lane gets partner (tg^1)'s pair -> contiguous float4
                    float o0 = __shfl_xor_sync(0xffffffffu, v0, 1);
                    float o1 = __shfl_xor_sync(0xffffffffu, v1, 1);
                    if ((tg & 1) == 0) {
                        const int n4 = n0 + wn + j * 8 + tg * 2;
                        if (rv && n4 < pOut) {
                            float a0 = v0, a1 = v1, a2 = o0, a3 = o1;
                            if (MODE == 1) {
                                const float4 xr = *reinterpret_cast<const float4*>(
                                    xg + (size_t)s_ * PP + n4);
                                a0 += xr.x; a1 += xr.y; a2 += xr.z; a3 += xr.w;
                            }
                            a0 = fmaxf(a0, 0.f); a1 = fmaxf(a1, 0.f);
                            a2 = fmaxf(a2, 0.f); a3 = fmaxf(a3, 0.f);
                            red4(outp + (size_t)d_ * pOut + n4, a0, a1, a2, a3);
                        }
                    }
                }
            }
        }
    }
}

// ---------------- head: g -> relu(g@Wl+bl) -> @Wl2+bl2 -> abs ----------------
__global__ void final_kernel(const float* __restrict__ g,
                             const float* __restrict__ Wl, const float* __restrict__ bl,
                             const float* __restrict__ Wl2, const float* __restrict__ bl2,
                             float* __restrict__ out)
{
    __shared__ float sg[200];
    __shared__ float s2[50];
    const int b = blockIdx.x;
    for (int i = threadIdx.x; i < 200; i += blockDim.x) sg[i] = g[(size_t)b * 200 + i];
    __syncthreads();
    if (threadIdx.x < 50) {
        float acc = bl[threadIdx.x];
        for (int k = 0; k < 200; ++k) acc = fmaf(sg[k], Wl[(size_t)k * 50 + threadIdx.x], acc);
        s2[threadIdx.x] = fmaxf(acc, 0.f);
    }
    __syncthreads();
    if (threadIdx.x == 0) {
        float o = bl2[0];
        for (int k = 0; k < 50; ++k) o = fmaf(s2[k], Wl2[k], o);
        out[b] = fabsf(o);
    }
}

// ---------------- launch ----------------
extern "C" void kernel_launch(void* const* d_in, const int* in_sizes, int n_in,
                              void* d_out, int out_size)
{
    const float* x    = (const float*)d_in[0];
    const int*   ei   = (const int*)  d_in[1];
    const float* ea   = (const float*)d_in[3];
    const int*   batch= (const int*)  d_in[4];
    const float* We1  = (const float*)d_in[5];
    const float* be1  = (const float*)d_in[6];
    const float* W1a  = (const float*)d_in[7];
    const float* b1a  = (const float*)d_in[8];
    const float* W1b  = (const float*)d_in[9];
    const float* b1b  = (const float*)d_in[10];
    const float* We2  = (const float*)d_in[11];
    const float* be2  = (const float*)d_in[12];
    const float* W2a  = (const float*)d_in[13];
    const float* b2a  = (const float*)d_in[14];
    const float* W2b  = (const float*)d_in[15];
    const float* b2b  = (const float*)d_in[16];
    const float* Wl   = (const float*)d_in[17];
    const float* bl   = (const float*)d_in[18];
    const float* Wl2  = (const float*)d_in[19];
    const float* bl2  = (const float*)d_in[20];

    const int* src = ei;
    const int* dst = ei + NE;

    __nv_bfloat16 *ea2, *as;
    float *xp, *agg, *tt, *h1, *gp;
    cudaGetSymbolAddress((void**)&ea2, g_ea2);
    cudaGetSymbolAddress((void**)&as,  g_as);
    cudaGetSymbolAddress((void**)&xp,  g_xp);
    cudaGetSymbolAddress((void**)&agg, g_agg);
    cudaGetSymbolAddress((void**)&tt,  g_t);
    cudaGetSymbolAddress((void**)&h1,  g_h1);
    cudaGetSymbolAddress((void**)&gp,  g_gp);

    cudaFuncSetAttribute(gemm_bf3<0>, cudaFuncAttributeMaxDynamicSharedMemorySize, SM_ALL);
    cudaFuncSetAttribute(gemm_bf3<1>, cudaFuncAttributeMaxDynamicSharedMemorySize, SM_ALL);
    cudaFuncSetAttribute(gemm_bf3<2>, cudaFuncAttributeMaxDynamicSharedMemorySize, SM_ALL);

    const int nodeBlocks = (NN + 127) / 128;   // 391
    const int edgeBlocks = NE / 128;           // 6250

    // ---- prep: split edge_attr (once per call), pad x plain ----
    {
        long long t = (long long)NE * 56;
        split_pair_kernel<<<(int)((t + 255) / 256), 256>>>(ea2, ea, NE, DD);
    }
    pad_plain_kernel<<<(NN * PP + 255) / 256, 256>>>(xp, x, NN, DD);

    const int nsplitBlocks = (int)(((long long)NN * 56 + 255) / 256);

    // ---- layer 1 ----
    cudaMemsetAsync(agg, 0, sizeof(float) * (size_t)NN * PP);
    gemm_bf3<1><<<dim3(edgeBlocks, 1), 256, SM_ALL>>>(ea2, We1, be1, NE, DD, DD,
                                                      src, dst, xp, agg, PP);
    add_split_kernel<<<nsplitBlocks, 256>>>(as, xp, agg);
    gemm_bf3<0><<<dim3(nodeBlocks, 1), 256, SM_ALL>>>(as, W1a, b1a, NN, DD, DD,
                                                      nullptr, nullptr, nullptr, tt, PP);
    split_pair_kernel<<<nsplitBlocks, 256>>>(as, tt, NN, PP);
    gemm_bf3<0><<<dim3(nodeBlocks, 1), 256, SM_ALL>>>(as, W1b, b1b, NN, DD, DD,
                                                      nullptr, nullptr, nullptr, h1, PP);

    // ---- layer 2 ----
    cudaMemsetAsync(agg, 0, sizeof(float) * (size_t)NN * PP);
    gemm_bf3<1><<<dim3(edgeBlocks, 1), 256, SM_ALL>>>(ea2, We2, be2, NE, DD, DD,
                                                      src, dst, h1, agg, PP);
    add_split_kernel<<<nsplitBlocks, 256>>>(as, h1, agg);
    gemm_bf3<0><<<dim3(nodeBlocks, 1), 256, SM_ALL>>>(as, W2a, b2a, NN, 100, DD,
                                                      nullptr, nullptr, nullptr, tt, PP);
    split_pair_kernel<<<nsplitBlocks, 256>>>(as, tt, NN, PP);
    cudaMemsetAsync(gp, 0, sizeof(float) * NG * 200);
    gemm_bf3<2><<<dim3(nodeBlocks, 2), 256, SM_ALL>>>(as, W2b, b2b, NN, 200, 100,
                                                      batch, nullptr, nullptr, gp, 200);

    // ---- head ----
    final_kernel<<<NG, 64>>>(gp, Wl, bl, Wl2, bl2, (float*)d_out);
}

// round 11
// speedup vs baseline: 1.5737x; 1.0521x over previous
#include <cuda_runtime.h>
#include <cuda_bf16.h>
#include <cstdint>
#include <cstddef>

#define NN   50000
#define NNP  50048      // padded rows (multiple of 128)
#define NE   800000
#define NG   512
#define DD   101
#define PP   104        // plain fp32 pitch (16B-aligned rows: 104*4=416)
#define RS   112        // split region size (bf16 cols per half; 7 k16-tiles)
#define PA   224        // split bf16 pitch = 2*RS (448B rows, 16B aligned)
#define NKT  21         // logical k16 tiles = 3 regions * 7

// smem partition (bytes): 4-stage A pipeline + weight cache + bias
#define SM_AS   24576              // uint32 As[4][128][12]
#define SM_WC   60928              // uint32 Wc[2][56][136]
#define SM_ALL  (SM_AS + SM_WC + 512)

// ---------------- scratch (device globals; zero-initialized; no allocation) ------
__device__ __nv_bfloat16 g_ea2[(size_t)NE * PA];   // edge_attr split [hi|lo] bf16
__device__ __nv_bfloat16 g_as [(size_t)NNP * PA];  // node GEMM input split (reused)
__device__ float g_xp [(size_t)NNP * PP];          // x padded, plain fp32
__device__ float g_agg[(size_t)NNP * PP];          // scatter-add target
__device__ float g_t  [(size_t)NNP * PP];          // MLP intermediate (plain)
__device__ float g_h1 [(size_t)NNP * PP];          // layer-1 output (plain)
__device__ float g_gp [NG * 200];                  // pooled per-graph features

// ---------------- helpers ----------------
__device__ __forceinline__ void red4(float* p, float a, float b, float c, float d) {
    asm volatile("red.global.add.v4.f32 [%0], {%1,%2,%3,%4};"
                 :: "l"(p), "f"(a), "f"(b), "f"(c), "f"(d) : "memory");
}

__device__ __forceinline__ uint32_t packbf(float e, float o) {
    __nv_bfloat162 t = __floats2bfloat162_rn(e, o);   // e -> low 16 bits (k even)
    return *reinterpret_cast<uint32_t*>(&t);
}

// split pair (v0,v1) into bf16 hi-pair and lo-pair (packed u32 each)
__device__ __forceinline__ void bsplit2(float v0, float v1, uint32_t& hi, uint32_t& lo) {
    float h0 = __bfloat162float(__float2bfloat16(v0));
    float h1 = __bfloat162float(__float2bfloat16(v1));
    hi = packbf(h0, h1);
    lo = packbf(v0 - h0, v1 - h1);
}

__device__ __forceinline__ void mma16816(float c[4],
                                         uint32_t a0, uint32_t a1, uint32_t a2, uint32_t a3,
                                         uint32_t b0, uint32_t b1) {
    asm volatile(
        "mma.sync.aligned.m16n8k16.row.col.f32.bf16.bf16.f32 "
        "{%0,%1,%2,%3}, {%4,%5,%6,%7}, {%8,%9}, {%0,%1,%2,%3};"
        : "+f"(c[0]), "+f"(c[1]), "+f"(c[2]), "+f"(c[3])
        : "r"(a0), "r"(a1), "r"(a2), "r"(a3), "r"(b0), "r"(b1));
}

// ---------------- prep kernels ----------------
// plain pad: src [rows x srcPitch] -> dst [rows x PP] fp32 (zeros in pad cols)
__global__ void pad_plain_kernel(float* __restrict__ dst, const float* __restrict__ src,
                                 int rows, int srcPitch) {
    int t = blockIdx.x * blockDim.x + threadIdx.x;
    if (t < rows * PP) {
        int r = t / PP;
        int c = t - r * PP;
        dst[t] = (c < srcPitch) ? __ldg(&src[(size_t)r * srcPitch + c]) : 0.f;
    }
}

// split: src plain [rows x srcPitch] fp32 -> dst [rows x PA] bf16 [hi(112)|lo(112)]
__global__ void split_pair_kernel(__nv_bfloat16* __restrict__ dst,
                                  const float* __restrict__ src,
                                  int rows, int srcPitch) {
    long long t = (long long)blockIdx.x * blockDim.x + threadIdx.x;
    if (t >= (long long)rows * 56) return;
    int r  = (int)(t / 56);
    int c2 = (int)(t % 56) * 2;
    float v0 = (c2     < srcPitch) ? __ldg(&src[(size_t)r * srcPitch + c2    ]) : 0.f;
    float v1 = (c2 + 1 < srcPitch) ? __ldg(&src[(size_t)r * srcPitch + c2 + 1]) : 0.f;
    uint32_t hi, lo;
    bsplit2(v0, v1, hi, lo);
    uint32_t* d32 = reinterpret_cast<uint32_t*>(dst + (size_t)r * PA);
    d32[c2 / 2]      = hi;
    d32[56 + c2 / 2] = lo;
}

// dst = split(a + b), a/b plain [NN x PP]
__global__ void add_split_kernel(__nv_bfloat16* __restrict__ dst,
                                 const float* __restrict__ a,
                                 const float* __restrict__ b) {
    long long t = (long long)blockIdx.x * blockDim.x + threadIdx.x;
    if (t >= (long long)NN * 56) return;
    int r  = (int)(t / 56);
    int c2 = (int)(t % 56) * 2;
    float v0 = 0.f, v1 = 0.f;
    if (c2 < PP)     v0 = a[(size_t)r * PP + c2]     + b[(size_t)r * PP + c2];
    if (c2 + 1 < PP) v1 = a[(size_t)r * PP + c2 + 1] + b[(size_t)r * PP + c2 + 1];
    uint32_t hi, lo;
    bsplit2(v0, v1, hi, lo);
    uint32_t* d32 = reinterpret_cast<uint32_t*>(dst + (size_t)r * PA);
    d32[c2 / 2]      = hi;
    d32[56 + c2 / 2] = lo;
}

// ---------------- 3xBF16 (K-expanded) tensor-core GEMM, fused epilogues ----------
// Logical K = 336 (3 regions of 112): A regions [hi|lo|hi], B regions [hi|hi|lo]
// => sum = hiA*hiB + loA*hiB + hiA*loB  (near-fp32 product accuracy)
// Block 128x128, 8 warps, warp tile 32x64. A via cp.async 4-stage pipeline
// (wait_group 2 -> 3 tiles in flight, covers DRAM latency);
// full weight tile (hi+lo) cached in smem once per block.
// MODE 0: outp[m][n] = relu(C+bias), plain fp32, zeros in pad cols up to pOut
// MODE 1: v = relu(C+bias+xg[idx0[m]][n]); red4 into outp[idx1[m]]  (edge message)
// MODE 2: v = relu(C+bias);                red4 into outp[idx0[m]]  (pool by batch)
template <int MODE>
__global__ __launch_bounds__(256, 2)
void gemm_bf3(const __nv_bfloat16* __restrict__ A,   // [M x PA] split bf16
              const float* __restrict__ B,           // [Korig x N] fp32 weights
              const float* __restrict__ bias,
              int M, int N, int Korig,
              const int* __restrict__ idx0, const int* __restrict__ idx1,
              const float* __restrict__ xg,          // plain fp32 [x PP]
              float* __restrict__ outp, int pOut)
{
    extern __shared__ char sm[];
    uint32_t* AsU   = reinterpret_cast<uint32_t*>(sm);            // [4][128][12]
    uint32_t* WcU   = reinterpret_cast<uint32_t*>(sm + SM_AS);    // [2][56][136]
    float*    biasS = reinterpret_cast<float*>(sm + SM_AS + SM_WC);

    const int tid  = threadIdx.x;
    const int m0   = blockIdx.x * 128;
    const int n0   = blockIdx.y * 128;
    const int wid  = tid >> 5;
    const int lane = tid & 31;
    const int wm   = (wid >> 1) * 32;
    const int wn   = (wid & 1) * 64;
    const int g    = lane >> 2;
    const int tg   = lane & 3;

    // A cp.async mapping: 2 threads per row, 16B each (32B = 16 bf16 per row-tile)
    const int arow = tid >> 1;
    const int aoff = (tid & 1);   // 0/1 -> +0/+16 bytes

    const char* Abase = reinterpret_cast<const char*>(A) + (size_t)(m0 + arow) * (PA * 2);

    // issue A tile kt into stage st (own commit group)
    auto issueA = [&](int kt, int st) {
        int r = (kt >= 14) ? 2 : (kt >= 7 ? 1 : 0);
        int q = kt - ((r == 2) ? 14 : (r == 1 ? 7 : 0));
        int physB = ((r == 1) ? (RS * 2) : 0) + q * 32 + aoff * 16;
        uint32_t sdst = (uint32_t)__cvta_generic_to_shared(
            AsU + st * (128 * 12) + arow * 12 + aoff * 4);
        asm volatile("cp.async.cg.shared.global [%0], [%1], 16;"
                     :: "r"(sdst), "l"(Abase + physB));
        asm volatile("cp.async.commit_group;");
    };

    issueA(0, 0);   // overlap stage-0 load with weight-cache fill

    // ---- fill weight cache: hi set + lo set, packed bf16 pairs ----
    for (int it = tid; it < 56 * 128; it += 256) {
        int kp = it >> 7, n = it & 127;
        int ke = kp * 2, ko = ke + 1;
        bool nv = (n0 + n < N);
        float we = (nv && ke < Korig) ? __ldg(&B[(size_t)ke * N + n0 + n]) : 0.f;
        float wo = (nv && ko < Korig) ? __ldg(&B[(size_t)ko * N + n0 + n]) : 0.f;
        uint32_t hi, lo;
        bsplit2(we, wo, hi, lo);
        WcU[kp * 136 + n]            = hi;
        WcU[56 * 136 + kp * 136 + n] = lo;
    }
    if (tid < 128) biasS[tid] = (n0 + tid < N) ? __ldg(&bias[n0 + tid]) : 0.f;

    issueA(1, 1);
    issueA(2, 2);

    float acc[2][8][4];
#pragma unroll
    for (int i = 0; i < 2; ++i)
#pragma unroll
        for (int j = 0; j < 8; ++j)
#pragma unroll
            for (int q = 0; q < 4; ++q) acc[i][j][q] = 0.f;

    for (int kt = 0; kt < NKT; ++kt) {
        const int st = kt & 3;
        // groups committed so far: kt+3 total; wait until <=2 pending -> group kt done
        asm volatile("cp.async.wait_group 2;");
        __syncthreads();   // also makes all warps done reading stage (kt+4)&3's slot

        if (kt + 3 < NKT) issueA(kt + 3, (kt + 3) & 3);
        else              asm volatile("cp.async.commit_group;");  // keep group count

        const int r   = (kt >= 14) ? 2 : (kt >= 7 ? 1 : 0);
        const int q   = kt - ((r == 2) ? 14 : (r == 1 ? 7 : 0));
        const uint32_t* wb = WcU + ((r == 2) ? 56 * 136 : 0) + (q * 8) * 136;

        uint32_t bfr[8][2];
#pragma unroll
        for (int j = 0; j < 8; ++j) {
            const int col = wn + j * 8 + g;
            bfr[j][0] = wb[tg * 136 + col];
            bfr[j][1] = wb[(tg + 4) * 136 + col];
        }
        const uint32_t* as = AsU + st * (128 * 12);
#pragma unroll
        for (int i = 0; i < 2; ++i) {
            const int mb = wm + i * 16 + g;
            uint32_t a0 = as[mb * 12 + tg];
            uint32_t a1 = as[(mb + 8) * 12 + tg];
            uint32_t a2 = as[mb * 12 + tg + 4];
            uint32_t a3 = as[(mb + 8) * 12 + tg + 4];
#pragma unroll
            for (int j = 0; j < 8; ++j)
                mma16816(acc[i][j], a0, a1, a2, a3, bfr[j][0], bfr[j][1]);
        }
    }

    // ---------------- epilogue ----------------
    if (MODE == 0) {
#pragma unroll
        for (int i = 0; i < 2; ++i) {
            const int rl = m0 + wm + i * 16 + g;
            const int rh = rl + 8;
#pragma unroll
            for (int j = 0; j < 8; ++j) {
                const int nl = wn + j * 8 + tg * 2;
                const int n  = n0 + nl;
                if (n < pOut) {
                    if (rl < M) {
                        float2 v;
                        v.x = fmaxf(acc[i][j][0] + biasS[nl], 0.f);
                        v.y = fmaxf(acc[i][j][1] + biasS[nl + 1], 0.f);
                        *reinterpret_cast<float2*>(&outp[(size_t)rl * pOut + n]) = v;
                    }
                    if (rh < M) {
                        float2 v;
                        v.x = fmaxf(acc[i][j][2] + biasS[nl], 0.f);
                        v.y = fmaxf(acc[i][j][3] + biasS[nl + 1], 0.f);
                        *reinterpret_cast<float2*>(&outp[(size_t)rh * pOut + n]) = v;
                    }
                }
            }
        }
    } else {
#pragma unroll
        for (int i = 0; i < 2; ++i) {
#pragma unroll
            for (int half = 0; half < 2; ++half) {
                const int r = m0 + wm + i * 16 + g + half * 8;
                const bool rv = (r < M);
                int s_ = 0, d_ = 0;
                if (rv) {
                    if (MODE == 1) { s_ = idx0[r]; d_ = idx1[r]; }
                    else           { d_ = idx0[r]; }
                }
#pragma unroll
                for (int j = 0; j < 8; ++j) {
                    const int nl = wn + j * 8 + tg * 2;
                    float v0 = acc[i][j][half * 2 + 0] + biasS[nl];
                    float v1 = acc[i][j][half * 2 + 1] + biasS[nl + 1];
                    // repack: lane gets partner (tg^1)'s pair -> contiguous float4
                    float o0 = __shfl_xor_sync(0xffffffffu, v0, 1);
                    float o1 = __shfl_xor_sync(0xffffffffu, v1, 1);
                    if ((tg & 1) == 0) {
                        const int n4 = n0 + wn + j * 8 + tg * 2;
                        if (rv && n4 < pOut) {
                            float a0 = v0, a1 = v1, a2 = o0, a3 = o1;
                            if (MODE == 1) {
                                const float4 xr = *reinterpret_cast<const float4*>(
                                    xg + (size_t)s_ * PP + n4);
                                a0 += xr.x; a1 += xr.y; a2 += xr.z; a3 += xr.w;
                            }
                            a0 = fmaxf(a0, 0.f); a1 = fmaxf(a1, 0.f);
                            a2 = fmaxf(a2, 0.f); a3 = fmaxf(a3, 0.f);
                            red4(outp + (size_t)d_ * pOut + n4, a0, a1, a2, a3);
                        }
                    }
                }
            }
        }
    }
}

// ---------------- head: g -> relu(g@Wl+bl) -> @Wl2+bl2 -> abs ----------------
__global__ void final_kernel(const float* __restrict__ g,
                             const float* __restrict__ Wl, const float* __restrict__ bl,
                             const float* __restrict__ Wl2, const float* __restrict__ bl2,
                             float* __restrict__ out)
{
    __shared__ float sg[200];
    __shared__ float s2[50];
    const int b = blockIdx.x;
    for (int i = threadIdx.x; i < 200; i += blockDim.x) sg[i] = g[(size_t)b * 200 + i];
    __syncthreads();
    if (threadIdx.x < 50) {
        float acc = bl[threadIdx.x];
        for (int k = 0; k < 200; ++k) acc = fmaf(sg[k], Wl[(size_t)k * 50 + threadIdx.x], acc);
        s2[threadIdx.x] = fmaxf(acc, 0.f);
    }
    __syncthreads();
    if (threadIdx.x == 0) {
        float o = bl2[0];
        for (int k = 0; k < 50; ++k) o = fmaf(s2[k], Wl2[k], o);
        out[b] = fabsf(o);
    }
}

// ---------------- launch ----------------
extern "C" void kernel_launch(void* const* d_in, const int* in_sizes, int n_in,
                              void* d_out, int out_size)
{
    const float* x    = (const float*)d_in[0];
    const int*   ei   = (const int*)  d_in[1];
    const float* ea   = (const float*)d_in[3];
    const int*   batch= (const int*)  d_in[4];
    const float* We1  = (const float*)d_in[5];
    const float* be1  = (const float*)d_in[6];
    const float* W1a  = (const float*)d_in[7];
    const float* b1a  = (const float*)d_in[8];
    const float* W1b  = (const float*)d_in[9];
    const float* b1b  = (const float*)d_in[10];
    const float* We2  = (const float*)d_in[11];
    const float* be2  = (const float*)d_in[12];
    const float* W2a  = (const float*)d_in[13];
    const float* b2a  = (const float*)d_in[14];
    const float* W2b  = (const float*)d_in[15];
    const float* b2b  = (const float*)d_in[16];
    const float* Wl   = (const float*)d_in[17];
    const float* bl   = (const float*)d_in[18];
    const float* Wl2  = (const float*)d_in[19];
    const float* bl2  = (const float*)d_in[20];

    const int* src = ei;
    const int* dst = ei + NE;

    __nv_bfloat16 *ea2, *as;
    float *xp, *agg, *tt, *h1, *gp;
    cudaGetSymbolAddress((void**)&ea2, g_ea2);
    cudaGetSymbolAddress((void**)&as,  g_as);
    cudaGetSymbolAddress((void**)&xp,  g_xp);
    cudaGetSymbolAddress((void**)&agg, g_agg);
    cudaGetSymbolAddress((void**)&tt,  g_t);
    cudaGetSymbolAddress((void**)&h1,  g_h1);
    cudaGetSymbolAddress((void**)&gp,  g_gp);

    cudaFuncSetAttribute(gemm_bf3<0>, cudaFuncAttributeMaxDynamicSharedMemorySize, SM_ALL);
    cudaFuncSetAttribute(gemm_bf3<1>, cudaFuncAttributeMaxDynamicSharedMemorySize, SM_ALL);
    cudaFuncSetAttribute(gemm_bf3<2>, cudaFuncAttributeMaxDynamicSharedMemorySize, SM_ALL);

    const int nodeBlocks = (NN + 127) / 128;   // 391
    const int edgeBlocks = NE / 128;           // 6250

    // ---- prep: split edge_attr (once per call), pad x plain ----
    {
        long long t = (long long)NE * 56;
        split_pair_kernel<<<(int)((t + 255) / 256), 256>>>(ea2, ea, NE, DD);
    }
    pad_plain_kernel<<<(NN * PP + 255) / 256, 256>>>(xp, x, NN, DD);

    const int nsplitBlocks = (int)(((long long)NN * 56 + 255) / 256);

    // ---- layer 1 ----
    cudaMemsetAsync(agg, 0, sizeof(float) * (size_t)NN * PP);
    gemm_bf3<1><<<dim3(edgeBlocks, 1), 256, SM_ALL>>>(ea2, We1, be1, NE, DD, DD,
                                                      src, dst, xp, agg, PP);
    add_split_kernel<<<nsplitBlocks, 256>>>(as, xp, agg);
    gemm_bf3<0><<<dim3(nodeBlocks, 1), 256, SM_ALL>>>(as, W1a, b1a, NN, DD, DD,
                                                      nullptr, nullptr, nullptr, tt, PP);
    split_pair_kernel<<<nsplitBlocks, 256>>>(as, tt, NN, PP);
    gemm_bf3<0><<<dim3(nodeBlocks, 1), 256, SM_ALL>>>(as, W1b, b1b, NN, DD, DD,
                                                      nullptr, nullptr, nullptr, h1, PP);

    // ---- layer 2 ----
    cudaMemsetAsync(agg, 0, sizeof(float) * (size_t)NN * PP);
    gemm_bf3<1><<<dim3(edgeBlocks, 1), 256, SM_ALL>>>(ea2, We2, be2, NE, DD, DD,
                                                      src, dst, h1, agg, PP);
    add_split_kernel<<<nsplitBlocks, 256>>>(as, h1, agg);
    gemm_bf3<0><<<dim3(nodeBlocks, 1), 256, SM_ALL>>>(as, W2a, b2a, NN, 100, DD,
                                                      nullptr, nullptr, nullptr, tt, PP);
    split_pair_kernel<<<nsplitBlocks, 256>>>(as, tt, NN, PP);
    cudaMemsetAsync(gp, 0, sizeof(float) * NG * 200);
    gemm_bf3<2><<<dim3(nodeBlocks, 2), 256, SM_ALL>>>(as, W2b, b2b, NN, 200, 100,
                                                      batch, nullptr, nullptr, gp, 200);

    // ---- head ----
    final_kernel<<<NG, 64>>>(gp, Wl, bl, Wl2, bl2, (float*)d_out);
}